// round 14
// baseline (speedup 1.0000x reference)
#include <cuda_runtime.h>
#include <cuda_fp16.h>
#include <cstdint>

// ---------------- problem constants ----------------
#define BB   8
#define TT   2048
#define CC   1024
#define EE   8
#define HH   4096
#define CAP  320
#define NTOK (BB * TT)
#define NASN (NTOK * 2)
#define ROWSE (BB * CAP)          // 2560

// ---------------- scratch ----------------
static __device__ __half g_xh [(size_t)NTOK * CC],  g_xl [(size_t)NTOK * CC];
static __device__ __half g_h1h[(size_t)NTOK * HH],  g_h1l[(size_t)NTOK * HH];
static __device__ float  g_plog[(size_t)NTOK * 256];   // [token][32 ntiles][8 experts]
static __device__ __half g_xeh[(size_t)EE * ROWSE * CC];
static __device__ __half g_heh[(size_t)EE * ROWSE * HH];
static __device__ float  g_ye [(size_t)EE * ROWSE * CC];
static __device__ __half g_rW1h[(size_t)HH * CC],      g_rW1l[(size_t)HH * CC];
static __device__ __half g_rW2h[(size_t)HH * HH],      g_rW2l[(size_t)HH * HH];
static __device__ __half g_eW1h[(size_t)EE * HH * CC];
static __device__ __half g_eW2h[(size_t)EE * CC * HH];
static __device__ int    g_expert[NASN];
static __device__ float  g_gate[NASN];
static __device__ int    g_pos[NASN];

// ---------------- helpers ----------------
__device__ __forceinline__ uint32_t smem_u32(const void* p) {
    uint32_t a;
    asm("{ .reg .u64 t; cvta.to.shared.u64 t, %1; cvt.u32.u64 %0, t; }" : "=r"(a) : "l"(p));
    return a;
}
__device__ __forceinline__ void mma_f16(float* c, const uint32_t* a, uint32_t b0, uint32_t b1) {
    asm("mma.sync.aligned.m16n8k16.row.col.f32.f16.f16.f32 "
        "{%0,%1,%2,%3}, {%4,%5,%6,%7}, {%8,%9}, {%0,%1,%2,%3};"
        : "+f"(c[0]), "+f"(c[1]), "+f"(c[2]), "+f"(c[3])
        : "r"(a[0]), "r"(a[1]), "r"(a[2]), "r"(a[3]), "r"(b0), "r"(b1));
}
#define LDMX4(R, ADDR) \
    asm volatile("ldmatrix.sync.aligned.m8n8.x4.shared.b16 {%0,%1,%2,%3}, [%4];" \
        : "=r"((R)[0]), "=r"((R)[1]), "=r"((R)[2]), "=r"((R)[3]) : "r"(ADDR))
#define CPA16(DST, SRC) \
    asm volatile("cp.async.cg.shared.global [%0], [%1], 16;" :: "r"(DST), "l"(SRC))
#define CPA_COMMIT() asm volatile("cp.async.commit_group;" ::: "memory")
#define CPA_WAIT1()  asm volatile("cp.async.wait_group 1;" ::: "memory")

// tile: 128 rows x 64 B (32 halves). phys(row, chunk) = row*64 + ((chunk ^ ((row>>1)&3))<<4)
#define TILEB 8192
__device__ __forceinline__ uint32_t physoff(int row, int chunk) {
    return (uint32_t)(row * 64 + (((chunk) ^ ((row >> 1) & 3)) << 4));
}

// ---------------- FP16 mma.sync GEMM, cp.async 3-stage, K-chunk 32, 1 sync/chunk ----
// A f16 hi(/lo) [M,K]; Bt f16 hi(/lo) [N,K]. PASSES=3: AhBh+AlBh+AhBl; PASSES=1: AhBh.
// OUT: 0 = f32, 1 = split f16 hi/lo, 2 = f16 hi only,
//      3 = fused partial logits (relu tile @ rW3 slice -> plogg, no C store).
template <int PASSES, bool RELU, int OUT>
__global__ __launch_bounds__(256, 2)
void hmma_gemm(const __half* __restrict__ Ahg, const __half* __restrict__ Alg,
               const __half* __restrict__ Bhg, const __half* __restrict__ Blg,
               const float* __restrict__ biasg,
               float* __restrict__ Cfg, __half* __restrict__ Chg, __half* __restrict__ Clg,
               const float* __restrict__ rW3g, float* __restrict__ plogg,
               int N, int K,
               long long sA, long long sB, long long sBias, long long sC)
{
    constexpr int NT_TILES = (PASSES == 3) ? 4 : 2;
    constexpr uint32_t OFF_AH = 0;
    constexpr uint32_t OFF_AL = TILEB;                 // only PASSES==3
    constexpr uint32_t OFF_BH = (PASSES == 3) ? 2 * TILEB : TILEB;
    constexpr uint32_t OFF_BL = 3 * TILEB;
    constexpr uint32_t STAGE_B = NT_TILES * TILEB;

    extern __shared__ __half sm[];
    const uint32_t sb = smem_u32(sm);
    const int tid  = threadIdx.x;
    const int wid  = tid >> 5;
    const int lane = tid & 31;
    const int q    = lane & 3;

    const size_t aBase = blockIdx.z * sA + (size_t)blockIdx.y * 128 * K;
    const size_t bBase = blockIdx.z * sB + (size_t)blockIdx.x * 128 * K;
    const float* bias  = biasg + blockIdx.z * sBias + blockIdx.x * 128;
    const size_t cBase = blockIdx.z * sC + (size_t)blockIdx.y * 128 * N + blockIdx.x * 128;

    // OUT==3: cache this CTA's 128-row slice of rW3 [4096][8] in smem (beyond stages)
    float* w3s   = reinterpret_cast<float*>((char*)sm + 3 * STAGE_B);
    float* plogs = w3s + 1024;
    if (OUT == 3)
        ((float4*)w3s)[tid] = ((const float4*)(rW3g + (size_t)blockIdx.x * 1024))[tid];

    const int wm = (wid & 3) * 32;      // warp tile 32x64
    const int wn = (wid >> 2) * 64;

    // ldmatrix per-lane byte offsets within a tile (swizzled), [mt or p][ks]
    const int r  = lane & 7;
    const int s0 = (lane >> 3) & 1;
    const int s1 = lane >> 4;
    uint32_t aoff[2][2], boff[4][2];
#pragma unroll
    for (int mt = 0; mt < 2; ++mt)
#pragma unroll
        for (int ks = 0; ks < 2; ++ks)
            aoff[mt][ks] = physoff(wm + 16 * mt + r + (s0 << 3), 2 * ks + s1);
#pragma unroll
    for (int p = 0; p < 4; ++p)
#pragma unroll
        for (int ks = 0; ks < 2; ++ks)
            boff[p][ks] = physoff(wn + 16 * p + r + (s1 << 3), 2 * ks + s0);

    // cp.async loader: row = tid>>1, seg = tid&1 -> logical chunks {2seg, 2seg+1}
    const int lrow = tid >> 1;
    const int lseg = tid & 1;
    const char* gAh = (const char*)(Ahg + aBase + (size_t)lrow * K) + lseg * 32;
    const char* gBh = (const char*)(Bhg + bBase + (size_t)lrow * K) + lseg * 32;
    const char* gAl = (PASSES == 3) ? (const char*)(Alg + aBase + (size_t)lrow * K) + lseg * 32 : nullptr;
    const char* gBl = (PASSES == 3) ? (const char*)(Blg + bBase + (size_t)lrow * K) + lseg * 32 : nullptr;
    const uint32_t d0 = physoff(lrow, 2 * lseg);
    const uint32_t d1 = physoff(lrow, 2 * lseg + 1);

    auto issue_chunk = [&](int t, int stage) {
        const uint32_t s = sb + (uint32_t)stage * STAGE_B;
        const int go = t << 6;                        // 64 bytes per chunk
        CPA16(s + OFF_AH + d0, gAh + go);
        CPA16(s + OFF_AH + d1, gAh + go + 16);
        CPA16(s + OFF_BH + d0, gBh + go);
        CPA16(s + OFF_BH + d1, gBh + go + 16);
        if (PASSES == 3) {
            CPA16(s + OFF_AL + d0, gAl + go);
            CPA16(s + OFF_AL + d1, gAl + go + 16);
            CPA16(s + OFF_BL + d0, gBl + go);
            CPA16(s + OFF_BL + d1, gBl + go + 16);
        }
    };

    float acc[2][8][4];
#pragma unroll
    for (int mt = 0; mt < 2; ++mt)
#pragma unroll
        for (int nt = 0; nt < 8; ++nt)
#pragma unroll
            for (int i = 0; i < 4; ++i) acc[mt][nt][i] = 0.f;

    const int T = K >> 5;

    issue_chunk(0, 0); CPA_COMMIT();
    issue_chunk(1, 1); CPA_COMMIT();

    int cur = 0;
    for (int t = 0; t < T; ++t) {
        CPA_WAIT1();
        __syncthreads();
        const int iss = (cur == 0) ? 2 : cur - 1;
        if (t + 2 < T) issue_chunk(t + 2, iss);
        CPA_COMMIT();

        const uint32_t stage = sb + (uint32_t)cur * STAGE_B;
#pragma unroll
        for (int ks = 0; ks < 2; ++ks) {
            uint32_t ah0[4], ah1[4], al0[4], al1[4];
            LDMX4(ah0, stage + OFF_AH + aoff[0][ks]);
            LDMX4(ah1, stage + OFF_AH + aoff[1][ks]);
            if (PASSES == 3) {
                LDMX4(al0, stage + OFF_AL + aoff[0][ks]);
                LDMX4(al1, stage + OFF_AL + aoff[1][ks]);
            }
#pragma unroll
            for (int p = 0; p < 4; ++p) {
                uint32_t bh[4], bl[4];
                LDMX4(bh, stage + OFF_BH + boff[p][ks]);
                if (PASSES == 3) LDMX4(bl, stage + OFF_BL + boff[p][ks]);
#pragma unroll
                for (int sub = 0; sub < 2; ++sub) {
                    const int nt = 2 * p + sub;
                    const uint32_t b0 = bh[2 * sub], b1 = bh[2 * sub + 1];
                    mma_f16(acc[0][nt], ah0, b0, b1);
                    mma_f16(acc[1][nt], ah1, b0, b1);
                    if (PASSES == 3) {
                        mma_f16(acc[0][nt], al0, b0, b1);
                        mma_f16(acc[1][nt], al1, b0, b1);
                        mma_f16(acc[0][nt], ah0, bl[2 * sub], bl[2 * sub + 1]);
                        mma_f16(acc[1][nt], ah1, bl[2 * sub], bl[2 * sub + 1]);
                    }
                }
            }
        }
        cur = (cur == 2) ? 0 : cur + 1;
    }

    const int gg = lane >> 2;

    if (OUT == 3) {
        // ---- fused partial logits: pl[mt][half][e] = sum_c relu(v)·w3[c][e] ----
        float pl[2][2][8];
#pragma unroll
        for (int mt = 0; mt < 2; ++mt)
#pragma unroll
            for (int h = 0; h < 2; ++h)
#pragma unroll
                for (int e = 0; e < 8; ++e) pl[mt][h][e] = 0.f;

#pragma unroll
        for (int nt = 0; nt < 8; ++nt) {
            const int cc = wn + 8 * nt + 2 * q;
            const float b0 = bias[cc], b1 = bias[cc + 1];
            const float4 w0a = *(const float4*)(w3s + cc * 8);
            const float4 w0b = *(const float4*)(w3s + cc * 8 + 4);
            const float4 w1a = *(const float4*)(w3s + (cc + 1) * 8);
            const float4 w1b = *(const float4*)(w3s + (cc + 1) * 8 + 4);
            const float w0[8] = {w0a.x, w0a.y, w0a.z, w0a.w, w0b.x, w0b.y, w0b.z, w0b.w};
            const float w1[8] = {w1a.x, w1a.y, w1a.z, w1a.w, w1b.x, w1b.y, w1b.z, w1b.w};
#pragma unroll
            for (int mt = 0; mt < 2; ++mt) {
                const float v0x = fmaxf(acc[mt][nt][0] + b0, 0.f);
                const float v0y = fmaxf(acc[mt][nt][1] + b1, 0.f);
                const float v1x = fmaxf(acc[mt][nt][2] + b0, 0.f);
                const float v1y = fmaxf(acc[mt][nt][3] + b1, 0.f);
#pragma unroll
                for (int e = 0; e < 8; ++e) {
                    pl[mt][0][e] += v0x * w0[e] + v0y * w1[e];
                    pl[mt][1][e] += v1x * w0[e] + v1y * w1[e];
                }
            }
        }
        // reduce over q lanes (deterministic butterfly within 4-lane groups)
#pragma unroll
        for (int mt = 0; mt < 2; ++mt)
#pragma unroll
            for (int h = 0; h < 2; ++h)
#pragma unroll
                for (int e = 0; e < 8; ++e) {
                    pl[mt][h][e] += __shfl_xor_sync(0xffffffffu, pl[mt][h][e], 1);
                    pl[mt][h][e] += __shfl_xor_sync(0xffffffffu, pl[mt][h][e], 2);
                }
        // two deterministic smem rounds: wn==0 warps init, wn==64 warps add
        __syncthreads();
        if (wn == 0 && q == 0) {
#pragma unroll
            for (int mt = 0; mt < 2; ++mt)
#pragma unroll
                for (int h = 0; h < 2; ++h) {
                    const int t = wm + 16 * mt + 8 * h + gg;
#pragma unroll
                    for (int e = 0; e < 8; ++e) plogs[t * 8 + e] = pl[mt][h][e];
                }
        }
        __syncthreads();
        if (wn == 64 && q == 0) {
#pragma unroll
            for (int mt = 0; mt < 2; ++mt)
#pragma unroll
                for (int h = 0; h < 2; ++h) {
                    const int t = wm + 16 * mt + 8 * h + gg;
#pragma unroll
                    for (int e = 0; e < 8; ++e) plogs[t * 8 + e] += pl[mt][h][e];
                }
        }
        __syncthreads();
        // store: g_plog[token][32][8]; token = by*128 + tid/2; float4 per thread
        const float4 val = *(const float4*)(plogs + tid * 4);
        const size_t tokG = (size_t)blockIdx.y * 128 + (tid >> 1);
        *(float4*)(plogg + tokG * 256 + blockIdx.x * 8 + (tid & 1) * 4) = val;
        return;
    }

    // ---- standard epilogue ----
#pragma unroll
    for (int nt = 0; nt < 8; ++nt) {
        const int c = wn + 8 * nt + 2 * q;
        const float b0 = bias[c], b1 = bias[c + 1];
#pragma unroll
        for (int mt = 0; mt < 2; ++mt) {
            const int rr = wm + 16 * mt + gg;
            float2 v0, v1;
            v0.x = acc[mt][nt][0] + b0; v0.y = acc[mt][nt][1] + b1;
            v1.x = acc[mt][nt][2] + b0; v1.y = acc[mt][nt][3] + b1;
            if (RELU) {
                v0.x = fmaxf(v0.x, 0.f); v0.y = fmaxf(v0.y, 0.f);
                v1.x = fmaxf(v1.x, 0.f); v1.y = fmaxf(v1.y, 0.f);
            }
            if (OUT == 0) {
                *(float2*)(Cfg + cBase + (size_t)rr * N + c)       = v0;
                *(float2*)(Cfg + cBase + (size_t)(rr + 8) * N + c) = v1;
            } else {
                __half2 h0 = __floats2half2_rn(v0.x, v0.y);
                __half2 h1 = __floats2half2_rn(v1.x, v1.y);
                *(__half2*)(Chg + cBase + (size_t)rr * N + c)       = h0;
                *(__half2*)(Chg + cBase + (size_t)(rr + 8) * N + c) = h1;
                if (OUT == 1) {
                    float2 f0 = __half22float2(h0);
                    float2 f1 = __half22float2(h1);
                    __half2 l0 = __floats2half2_rn(v0.x - f0.x, v0.y - f0.y);
                    __half2 l1 = __floats2half2_rn(v1.x - f1.x, v1.y - f1.y);
                    *(__half2*)(Clg + cBase + (size_t)rr * N + c)       = l0;
                    *(__half2*)(Clg + cBase + (size_t)(rr + 8) * N + c) = l1;
                }
            }
        }
    }
}

// ---------------- split fp32 -> f16 hi/lo ----------------
__global__ void split_f32(const float* __restrict__ in, __half* __restrict__ hi,
                          __half* __restrict__ lo, size_t n)
{
    const size_t i = ((size_t)blockIdx.x * blockDim.x + threadIdx.x) * 4;
    if (i >= n) return;
    const float4 v = *(const float4*)(in + i);
    __half2 h0 = __floats2half2_rn(v.x, v.y);
    __half2 h1 = __floats2half2_rn(v.z, v.w);
    float2 f0 = __half22float2(h0);
    float2 f1 = __half22float2(h1);
    __half2 l0 = __floats2half2_rn(v.x - f0.x, v.y - f0.y);
    __half2 l1 = __floats2half2_rn(v.z - f1.x, v.w - f1.y);
    *(__half2*)(hi + i)     = h0;
    *(__half2*)(hi + i + 2) = h1;
    *(__half2*)(lo + i)     = l0;
    *(__half2*)(lo + i + 2) = l1;
}

// ---------------- weight transpose + split (half2 coalesced stores) ----------------
__global__ void transpose_split_w(const float* __restrict__ W,
                                  __half* __restrict__ Wth, __half* __restrict__ Wtl,
                                  int K, int N, long long sIn, long long sOut)
{
    __shared__ float s[64][33];
    const float* Wz = W + blockIdx.z * sIn;
    __half* Wh = Wth + blockIdx.z * sOut;
    __half* Wl = Wtl ? (Wtl + blockIdx.z * sOut) : nullptr;
    const int nb = blockIdx.x * 32, kb = blockIdx.y * 64;
    const int tx = threadIdx.x, ty = threadIdx.y;   // 32 x 8
#pragma unroll
    for (int j = 0; j < 64; j += 8) s[ty + j][tx] = Wz[(size_t)(kb + ty + j) * N + nb + tx];
    __syncthreads();
#pragma unroll
    for (int jj = 0; jj < 4; ++jj) {
        const int n = ty + 8 * jj;
        const float v0 = s[2 * tx][n], v1 = s[2 * tx + 1][n];
        const __half2 h = __floats2half2_rn(v0, v1);
        const size_t o = (size_t)(nb + n) * K + kb + 2 * tx;
        *(__half2*)(Wh + o) = h;
        if (Wl) {
            const float2 f = __half22float2(h);
            *(__half2*)(Wl + o) = __floats2half2_rn(v0 - f.x, v1 - f.y);
        }
    }
}

// ---------------- final logits reduce + softmax + top2 ----------------
__global__ void logits_topk(const float* __restrict__ plog, const float* __restrict__ rb3)
{
    const int warp = (blockIdx.x * blockDim.x + threadIdx.x) >> 5;
    const int lane = threadIdx.x & 31;
    if (warp >= NTOK) return;
    const float4* p = (const float4*)(plog + (size_t)warp * 256 + lane * 8);
    const float4 a = p[0], b = p[1];
    float acc[8] = {a.x, a.y, a.z, a.w, b.x, b.y, b.z, b.w};
#pragma unroll
    for (int e = 0; e < 8; ++e)
#pragma unroll
        for (int off = 16; off > 0; off >>= 1)
            acc[e] += __shfl_xor_sync(0xffffffffu, acc[e], off);
    if (lane == 0) {
        float lg[8], mx = -1e30f;
#pragma unroll
        for (int e = 0; e < 8; ++e) { lg[e] = acc[e] + rb3[e]; mx = fmaxf(mx, lg[e]); }
        float sm[8], sum = 0.f;
#pragma unroll
        for (int e = 0; e < 8; ++e) { sm[e] = __expf(lg[e] - mx); sum += sm[e]; }
        const float inv = 1.f / sum;
#pragma unroll
        for (int e = 0; e < 8; ++e) sm[e] *= inv;
        int e1 = 0; float v1 = sm[0];
#pragma unroll
        for (int e = 1; e < 8; ++e) if (sm[e] > v1) { v1 = sm[e]; e1 = e; }
        int e2 = -1; float v2 = -1e30f;
#pragma unroll
        for (int e = 0; e < 8; ++e) {
            if (e == e1) continue;
            if (sm[e] > v2) { v2 = sm[e]; e2 = e; }
        }
        const int j = warp * 2;
        g_expert[j] = e1;     g_gate[j] = v1;
        g_expert[j + 1] = e2; g_gate[j + 1] = v2;
    }
}

// ---------------- per-(b,e) capacity scan: warp ballot scan ----------------
__global__ void scan_capacity()
{
    __shared__ int se[TT * 2];
    const int b = blockIdx.x;
    const int base = b * (TT * 2);
    for (int i = threadIdx.x; i < TT * 2; i += blockDim.x) se[i] = g_expert[base + i];
    __syncthreads();
    const int e = threadIdx.x >> 5;
    const int lane = threadIdx.x & 31;
    int cnt = 0;
    for (int i0 = 0; i0 < TT * 2; i0 += 32) {
        const bool m = (se[i0 + lane] == e);
        const unsigned bal = __ballot_sync(0xffffffffu, m);
        if (m) {
            const int pos = cnt + __popc(bal & ((1u << lane) - 1));
            g_pos[base + i0 + lane] = (pos < CAP) ? pos : -1;
        }
        cnt += __popc(bal);
    }
}

// ---------------- gather kept tokens ----------------
__global__ void scatter_x()
{
    const int j = blockIdx.x;
    const int pos = g_pos[j];
    if (pos < 0) return;
    const int e = g_expert[j];
    const int b = j / (TT * 2);
    const int t = (j % (TT * 2)) >> 1;
    const uint4* sh = (const uint4*)(g_xh + (size_t)(b * TT + t) * CC);
    uint4* dh = (uint4*)(g_xeh + ((size_t)e * ROWSE + b * CAP + pos) * CC);
    for (int c = threadIdx.x; c < CC / 8; c += blockDim.x) dh[c] = sh[c];
}

// ---------------- combine ----------------
__global__ void combine(float* __restrict__ out)
{
    const int tok = blockIdx.x;
    const int b = tok / TT;
    const int j = tok * 2;
    const int e0 = g_expert[j],     p0 = g_pos[j];     const float w0 = g_gate[j];
    const int e1 = g_expert[j + 1], p1 = g_pos[j + 1]; const float w1 = g_gate[j + 1];
    const float4* y0 = (p0 >= 0) ? (const float4*)(g_ye + ((size_t)e0 * ROWSE + b * CAP + p0) * CC) : nullptr;
    const float4* y1 = (p1 >= 0) ? (const float4*)(g_ye + ((size_t)e1 * ROWSE + b * CAP + p1) * CC) : nullptr;
    float4* o = (float4*)(out + (size_t)tok * CC);
    for (int c = threadIdx.x; c < CC / 4; c += blockDim.x) {
        float4 acc = make_float4(0.f, 0.f, 0.f, 0.f);
        if (y0) { float4 v = y0[c]; acc.x += w0 * v.x; acc.y += w0 * v.y; acc.z += w0 * v.z; acc.w += w0 * v.w; }
        if (y1) { float4 v = y1[c]; acc.x += w1 * v.x; acc.y += w1 * v.y; acc.z += w1 * v.z; acc.w += w1 * v.w; }
        o[c] = acc;
    }
}

// ---------------- launch ----------------
extern "C" void kernel_launch(void* const* d_in, const int* in_sizes, int n_in,
                              void* d_out, int out_size)
{
    const float* x   = (const float*)d_in[0];
    const float* rW1 = (const float*)d_in[1];
    const float* rb1 = (const float*)d_in[2];
    const float* rW2 = (const float*)d_in[3];
    const float* rb2 = (const float*)d_in[4];
    const float* rW3 = (const float*)d_in[5];
    const float* rb3 = (const float*)d_in[6];
    const float* eW1 = (const float*)d_in[7];
    const float* eb1 = (const float*)d_in[8];
    const float* eW2 = (const float*)d_in[9];
    const float* eb2 = (const float*)d_in[10];
    float* out = (float*)d_out;

    __half *xh, *xl, *h1h, *h1l, *xeh, *heh;
    __half *rW1h, *rW1l, *rW2h, *rW2l, *eW1h, *eW2h;
    float *ye, *plog;
    cudaGetSymbolAddress((void**)&xh, g_xh);   cudaGetSymbolAddress((void**)&xl, g_xl);
    cudaGetSymbolAddress((void**)&h1h, g_h1h); cudaGetSymbolAddress((void**)&h1l, g_h1l);
    cudaGetSymbolAddress((void**)&plog, g_plog);
    cudaGetSymbolAddress((void**)&xeh, g_xeh);
    cudaGetSymbolAddress((void**)&heh, g_heh);
    cudaGetSymbolAddress((void**)&ye, g_ye);
    cudaGetSymbolAddress((void**)&rW1h, g_rW1h); cudaGetSymbolAddress((void**)&rW1l, g_rW1l);
    cudaGetSymbolAddress((void**)&rW2h, g_rW2h); cudaGetSymbolAddress((void**)&rW2l, g_rW2l);
    cudaGetSymbolAddress((void**)&eW1h, g_eW1h);
    cudaGetSymbolAddress((void**)&eW2h, g_eW2h);

    const int smem3  = 3 * 4 * TILEB;            // 98304 B
    const int smem3f = smem3 + 8192;             // + rW3 slice + plog smem
    const int smem1  = 3 * 2 * TILEB;            // 49152 B
    cudaFuncSetAttribute(hmma_gemm<3, true,  1>, cudaFuncAttributeMaxDynamicSharedMemorySize, smem3);
    cudaFuncSetAttribute(hmma_gemm<3, true,  3>, cudaFuncAttributeMaxDynamicSharedMemorySize, smem3f);
    cudaFuncSetAttribute(hmma_gemm<1, true,  2>, cudaFuncAttributeMaxDynamicSharedMemorySize, smem1);
    cudaFuncSetAttribute(hmma_gemm<1, false, 0>, cudaFuncAttributeMaxDynamicSharedMemorySize, smem1);

    // input split + weight transpose/split
    split_f32<<<(NTOK * CC / 4 + 255) / 256, 256>>>(x, xh, xl, (size_t)NTOK * CC);
    transpose_split_w<<<dim3(HH / 32, CC / 64, 1),  dim3(32, 8)>>>(rW1, rW1h, rW1l, CC, HH, 0, 0);
    transpose_split_w<<<dim3(HH / 32, HH / 64, 1),  dim3(32, 8)>>>(rW2, rW2h, rW2l, HH, HH, 0, 0);
    transpose_split_w<<<dim3(HH / 32, CC / 64, EE), dim3(32, 8)>>>(eW1, eW1h, nullptr, CC, HH,
        (long long)CC * HH, (long long)HH * CC);
    transpose_split_w<<<dim3(CC / 32, HH / 64, EE), dim3(32, 8)>>>(eW2, eW2h, nullptr, HH, CC,
        (long long)HH * CC, (long long)CC * HH);

    // router layer 1: h1 = relu(x @ rW1 + rb1)  (3-pass, split f16 output)
    hmma_gemm<3, true, 1><<<dim3(HH / 128, NTOK / 128, 1), 256, smem3>>>(
        xh, xl, rW1h, rW1l, rb1, nullptr, h1h, h1l, nullptr, nullptr, HH, CC, 0, 0, 0, 0);
    // router layer 2 + fused logit projection: partial logits per N-tile (no h2)
    hmma_gemm<3, true, 3><<<dim3(HH / 128, NTOK / 128, 1), 256, smem3f>>>(
        h1h, h1l, rW2h, rW2l, rb2, nullptr, nullptr, nullptr, rW3, plog, HH, HH, 0, 0, 0, 0);
    // final logits reduce + softmax + top2
    logits_topk<<<(NTOK * 32) / 256, 256>>>(plog, rb3);
    // capacity positions
    scan_capacity<<<BB, 256>>>();
    // dispatch
    scatter_x<<<NASN, 128>>>();
    // expert layer 1: he = relu(xe @ eW1[e] + eb1[e])  (1-pass, f16 hi output)
    hmma_gemm<1, true, 2><<<dim3(HH / 128, ROWSE / 128, EE), 256, smem1>>>(
        xeh, nullptr, eW1h, nullptr, eb1, nullptr, heh, nullptr, nullptr, nullptr, HH, CC,
        (long long)ROWSE * CC, (long long)HH * CC, HH, (long long)ROWSE * HH);
    // expert layer 2: ye = he @ eW2[e] + eb2[e]  (1-pass, f32 output)
    hmma_gemm<1, false, 0><<<dim3(CC / 128, ROWSE / 128, EE), 256, smem1>>>(
        heh, nullptr, eW2h, nullptr, eb2, ye, nullptr, nullptr, nullptr, nullptr, CC, HH,
        (long long)ROWSE * HH, (long long)CC * HH, CC, (long long)ROWSE * CC);
    // combine
    combine<<<NTOK, 256>>>(out);
}

// round 15
// speedup vs baseline: 1.5367x; 1.5367x over previous
#include <cuda_runtime.h>
#include <cuda_fp16.h>
#include <cstdint>

// ---------------- problem constants ----------------
#define BB   8
#define TT   2048
#define CC   1024
#define EE   8
#define HH   4096
#define CAP  320
#define NTOK (BB * TT)
#define NASN (NTOK * 2)
#define ROWSE (BB * CAP)          // 2560

// ---------------- scratch ----------------
static __device__ __half g_xh [(size_t)NTOK * CC],  g_xl [(size_t)NTOK * CC];
static __device__ __half g_h1h[(size_t)NTOK * HH],  g_h1l[(size_t)NTOK * HH];
static __device__ float  g_h2 [(size_t)NTOK * HH];
static __device__ __half g_xeh[(size_t)EE * ROWSE * CC];
static __device__ __half g_heh[(size_t)EE * ROWSE * HH];
static __device__ float  g_ye [(size_t)EE * ROWSE * CC];
static __device__ __half g_rW1h[(size_t)HH * CC],      g_rW1l[(size_t)HH * CC];
static __device__ __half g_rW2h[(size_t)HH * HH],      g_rW2l[(size_t)HH * HH];
static __device__ __half g_eW1h[(size_t)EE * HH * CC];
static __device__ __half g_eW2h[(size_t)EE * CC * HH];
static __device__ int    g_expert[NASN];
static __device__ float  g_gate[NASN];
static __device__ int    g_pos[NASN];

// ---------------- helpers ----------------
__device__ __forceinline__ uint32_t smem_u32(const void* p) {
    uint32_t a;
    asm("{ .reg .u64 t; cvta.to.shared.u64 t, %1; cvt.u32.u64 %0, t; }" : "=r"(a) : "l"(p));
    return a;
}
__device__ __forceinline__ void mma_f16(float* c, const uint32_t* a, uint32_t b0, uint32_t b1) {
    asm("mma.sync.aligned.m16n8k16.row.col.f32.f16.f16.f32 "
        "{%0,%1,%2,%3}, {%4,%5,%6,%7}, {%8,%9}, {%0,%1,%2,%3};"
        : "+f"(c[0]), "+f"(c[1]), "+f"(c[2]), "+f"(c[3])
        : "r"(a[0]), "r"(a[1]), "r"(a[2]), "r"(a[3]), "r"(b0), "r"(b1));
}
#define LDMX4(R, ADDR) \
    asm volatile("ldmatrix.sync.aligned.m8n8.x4.shared.b16 {%0,%1,%2,%3}, [%4];" \
        : "=r"((R)[0]), "=r"((R)[1]), "=r"((R)[2]), "=r"((R)[3]) : "r"(ADDR))
#define CPA16(DST, SRC) \
    asm volatile("cp.async.cg.shared.global [%0], [%1], 16;" :: "r"(DST), "l"(SRC))
#define CPA_COMMIT() asm volatile("cp.async.commit_group;" ::: "memory")
#define CPA_WAIT1()  asm volatile("cp.async.wait_group 1;" ::: "memory")

// tile: 128 rows x 64 B (32 halves). phys(row, chunk) = row*64 + ((chunk ^ ((row>>1)&3))<<4)
// 8-row x 16B ldmatrix phases: even rows cover all 4 chunk slots (banks 0-15),
// odd rows cover banks 16-31 -> conflict-free.
#define TILEB 8192
__device__ __forceinline__ uint32_t physoff(int row, int chunk) {
    return (uint32_t)(row * 64 + (((chunk) ^ ((row >> 1) & 3)) << 4));
}

// ---------------- FP16 mma.sync GEMM, cp.async 3-stage, K-chunk 32, 1 sync/chunk ----
// A f16 hi(/lo) [M,K]; Bt f16 hi(/lo) [N,K]. PASSES=3: AhBh+AlBh+AhBl; PASSES=1: AhBh.
// OUT: 0 = f32, 1 = split f16 hi/lo, 2 = f16 hi only.
template <int PASSES, bool RELU, int OUT>
__global__ __launch_bounds__(256, 2)
void hmma_gemm(const __half* __restrict__ Ahg, const __half* __restrict__ Alg,
               const __half* __restrict__ Bhg, const __half* __restrict__ Blg,
               const float* __restrict__ biasg,
               float* __restrict__ Cfg, __half* __restrict__ Chg, __half* __restrict__ Clg,
               int N, int K,
               long long sA, long long sB, long long sBias, long long sC)
{
    constexpr int NT_TILES = (PASSES == 3) ? 4 : 2;
    constexpr uint32_t OFF_AH = 0;
    constexpr uint32_t OFF_AL = TILEB;                 // only PASSES==3
    constexpr uint32_t OFF_BH = (PASSES == 3) ? 2 * TILEB : TILEB;
    constexpr uint32_t OFF_BL = 3 * TILEB;
    constexpr uint32_t STAGE_B = NT_TILES * TILEB;

    extern __shared__ __half sm[];
    const uint32_t sb = smem_u32(sm);
    const int tid  = threadIdx.x;
    const int wid  = tid >> 5;
    const int lane = tid & 31;
    const int q    = lane & 3;

    const size_t aBase = blockIdx.z * sA + (size_t)blockIdx.y * 128 * K;
    const size_t bBase = blockIdx.z * sB + (size_t)blockIdx.x * 128 * K;
    const float* bias  = biasg + blockIdx.z * sBias + blockIdx.x * 128;
    const size_t cBase = blockIdx.z * sC + (size_t)blockIdx.y * 128 * N + blockIdx.x * 128;

    const int wm = (wid & 3) * 32;      // warp tile 32x64
    const int wn = (wid >> 2) * 64;

    // ldmatrix per-lane byte offsets within a tile (swizzled), [mt or p][ks]
    const int r  = lane & 7;
    const int s0 = (lane >> 3) & 1;
    const int s1 = lane >> 4;
    uint32_t aoff[2][2], boff[4][2];
#pragma unroll
    for (int mt = 0; mt < 2; ++mt)
#pragma unroll
        for (int ks = 0; ks < 2; ++ks)
            aoff[mt][ks] = physoff(wm + 16 * mt + r + (s0 << 3), 2 * ks + s1);
#pragma unroll
    for (int p = 0; p < 4; ++p)
#pragma unroll
        for (int ks = 0; ks < 2; ++ks)
            boff[p][ks] = physoff(wn + 16 * p + r + (s1 << 3), 2 * ks + s0);

    // cp.async loader: row = tid>>1, seg = tid&1 -> logical chunks {2seg, 2seg+1}
    const int lrow = tid >> 1;
    const int lseg = tid & 1;
    const char* gAh = (const char*)(Ahg + aBase + (size_t)lrow * K) + lseg * 32;
    const char* gBh = (const char*)(Bhg + bBase + (size_t)lrow * K) + lseg * 32;
    const char* gAl = (PASSES == 3) ? (const char*)(Alg + aBase + (size_t)lrow * K) + lseg * 32 : nullptr;
    const char* gBl = (PASSES == 3) ? (const char*)(Blg + bBase + (size_t)lrow * K) + lseg * 32 : nullptr;
    const uint32_t d0 = physoff(lrow, 2 * lseg);
    const uint32_t d1 = physoff(lrow, 2 * lseg + 1);

    auto issue_chunk = [&](int t, int stage) {
        const uint32_t s = sb + (uint32_t)stage * STAGE_B;
        const int go = t << 6;                        // 64 bytes per chunk
        CPA16(s + OFF_AH + d0, gAh + go);
        CPA16(s + OFF_AH + d1, gAh + go + 16);
        CPA16(s + OFF_BH + d0, gBh + go);
        CPA16(s + OFF_BH + d1, gBh + go + 16);
        if (PASSES == 3) {
            CPA16(s + OFF_AL + d0, gAl + go);
            CPA16(s + OFF_AL + d1, gAl + go + 16);
            CPA16(s + OFF_BL + d0, gBl + go);
            CPA16(s + OFF_BL + d1, gBl + go + 16);
        }
    };

    float acc[2][8][4];
#pragma unroll
    for (int mt = 0; mt < 2; ++mt)
#pragma unroll
        for (int nt = 0; nt < 8; ++nt)
#pragma unroll
            for (int i = 0; i < 4; ++i) acc[mt][nt][i] = 0.f;

    const int T = K >> 5;

    issue_chunk(0, 0); CPA_COMMIT();
    issue_chunk(1, 1); CPA_COMMIT();

    int cur = 0;
    for (int t = 0; t < T; ++t) {
        CPA_WAIT1();                    // chunk t landed
        __syncthreads();                // visibility + all warps done reading stage (t-1)%3
        const int iss = (cur == 0) ? 2 : cur - 1;   // (t+2)%3
        if (t + 2 < T) issue_chunk(t + 2, iss);
        CPA_COMMIT();

        const uint32_t stage = sb + (uint32_t)cur * STAGE_B;
#pragma unroll
        for (int ks = 0; ks < 2; ++ks) {
            uint32_t ah0[4], ah1[4], al0[4], al1[4];
            LDMX4(ah0, stage + OFF_AH + aoff[0][ks]);
            LDMX4(ah1, stage + OFF_AH + aoff[1][ks]);
            if (PASSES == 3) {
                LDMX4(al0, stage + OFF_AL + aoff[0][ks]);
                LDMX4(al1, stage + OFF_AL + aoff[1][ks]);
            }
#pragma unroll
            for (int p = 0; p < 4; ++p) {
                uint32_t bh[4], bl[4];
                LDMX4(bh, stage + OFF_BH + boff[p][ks]);
                if (PASSES == 3) LDMX4(bl, stage + OFF_BL + boff[p][ks]);
#pragma unroll
                for (int sub = 0; sub < 2; ++sub) {
                    const int nt = 2 * p + sub;
                    const uint32_t b0 = bh[2 * sub], b1 = bh[2 * sub + 1];
                    mma_f16(acc[0][nt], ah0, b0, b1);
                    mma_f16(acc[1][nt], ah1, b0, b1);
                    if (PASSES == 3) {
                        mma_f16(acc[0][nt], al0, b0, b1);
                        mma_f16(acc[1][nt], al1, b0, b1);
                        mma_f16(acc[0][nt], ah0, bl[2 * sub], bl[2 * sub + 1]);
                        mma_f16(acc[1][nt], ah1, bl[2 * sub], bl[2 * sub + 1]);
                    }
                }
            }
        }
        cur = (cur == 2) ? 0 : cur + 1;
    }

    // epilogue
    const int gg = lane >> 2;
#pragma unroll
    for (int nt = 0; nt < 8; ++nt) {
        const int c = wn + 8 * nt + 2 * q;
        const float b0 = bias[c], b1 = bias[c + 1];
#pragma unroll
        for (int mt = 0; mt < 2; ++mt) {
            const int rr = wm + 16 * mt + gg;
            float2 v0, v1;
            v0.x = acc[mt][nt][0] + b0; v0.y = acc[mt][nt][1] + b1;
            v1.x = acc[mt][nt][2] + b0; v1.y = acc[mt][nt][3] + b1;
            if (RELU) {
                v0.x = fmaxf(v0.x, 0.f); v0.y = fmaxf(v0.y, 0.f);
                v1.x = fmaxf(v1.x, 0.f); v1.y = fmaxf(v1.y, 0.f);
            }
            if (OUT == 0) {
                *(float2*)(Cfg + cBase + (size_t)rr * N + c)       = v0;
                *(float2*)(Cfg + cBase + (size_t)(rr + 8) * N + c) = v1;
            } else {
                __half2 h0 = __floats2half2_rn(v0.x, v0.y);
                __half2 h1 = __floats2half2_rn(v1.x, v1.y);
                *(__half2*)(Chg + cBase + (size_t)rr * N + c)       = h0;
                *(__half2*)(Chg + cBase + (size_t)(rr + 8) * N + c) = h1;
                if (OUT == 1) {
                    float2 f0 = __half22float2(h0);
                    float2 f1 = __half22float2(h1);
                    __half2 l0 = __floats2half2_rn(v0.x - f0.x, v0.y - f0.y);
                    __half2 l1 = __floats2half2_rn(v1.x - f1.x, v1.y - f1.y);
                    *(__half2*)(Clg + cBase + (size_t)rr * N + c)       = l0;
                    *(__half2*)(Clg + cBase + (size_t)(rr + 8) * N + c) = l1;
                }
            }
        }
    }
}

// ---------------- split fp32 -> f16 hi/lo ----------------
__global__ void split_f32(const float* __restrict__ in, __half* __restrict__ hi,
                          __half* __restrict__ lo, size_t n)
{
    const size_t i = ((size_t)blockIdx.x * blockDim.x + threadIdx.x) * 4;
    if (i >= n) return;
    const float4 v = *(const float4*)(in + i);
    __half2 h0 = __floats2half2_rn(v.x, v.y);
    __half2 h1 = __floats2half2_rn(v.z, v.w);
    float2 f0 = __half22float2(h0);
    float2 f1 = __half22float2(h1);
    __half2 l0 = __floats2half2_rn(v.x - f0.x, v.y - f0.y);
    __half2 l1 = __floats2half2_rn(v.z - f1.x, v.w - f1.y);
    *(__half2*)(hi + i)     = h0;
    *(__half2*)(hi + i + 2) = h1;
    *(__half2*)(lo + i)     = l0;
    *(__half2*)(lo + i + 2) = l1;
}

// ---------------- weight transpose + split: W [K,N] f32 -> Wt hi(/lo) [N,K] f16 ----
// 64(K) x 32(N) tiles; half2 coalesced stores (128B per warp).
__global__ void transpose_split_w(const float* __restrict__ W,
                                  __half* __restrict__ Wth, __half* __restrict__ Wtl,
                                  int K, int N, long long sIn, long long sOut)
{
    __shared__ float s[64][33];
    const float* Wz = W + blockIdx.z * sIn;
    __half* Wh = Wth + blockIdx.z * sOut;
    __half* Wl = Wtl ? (Wtl + blockIdx.z * sOut) : nullptr;
    const int nb = blockIdx.x * 32, kb = blockIdx.y * 64;
    const int tx = threadIdx.x, ty = threadIdx.y;   // 32 x 8
#pragma unroll
    for (int j = 0; j < 64; j += 8) s[ty + j][tx] = Wz[(size_t)(kb + ty + j) * N + nb + tx];
    __syncthreads();
#pragma unroll
    for (int jj = 0; jj < 4; ++jj) {
        const int n = ty + 8 * jj;                   // 0..31
        const float v0 = s[2 * tx][n], v1 = s[2 * tx + 1][n];
        const __half2 h = __floats2half2_rn(v0, v1);
        const size_t o = (size_t)(nb + n) * K + kb + 2 * tx;
        *(__half2*)(Wh + o) = h;
        if (Wl) {
            const float2 f = __half22float2(h);
            *(__half2*)(Wl + o) = __floats2half2_rn(v0 - f.x, v1 - f.y);
        }
    }
}

// ---------------- router final layer ----------------
__global__ void router_topk(const float* __restrict__ h2,
                            const float* __restrict__ rW3,
                            const float* __restrict__ rb3)
{
    const int warp = (blockIdx.x * blockDim.x + threadIdx.x) >> 5;
    const int lane = threadIdx.x & 31;
    if (warp >= NTOK) return;
    const float* hrow = h2 + (size_t)warp * HH;
    float acc[8] = {0.f, 0.f, 0.f, 0.f, 0.f, 0.f, 0.f, 0.f};
    for (int i = lane; i < HH; i += 32) {
        const float hv = hrow[i];
        const float4 w0 = *(const float4*)(rW3 + (size_t)i * 8);
        const float4 w1 = *(const float4*)(rW3 + (size_t)i * 8 + 4);
        acc[0] += hv * w0.x; acc[1] += hv * w0.y; acc[2] += hv * w0.z; acc[3] += hv * w0.w;
        acc[4] += hv * w1.x; acc[5] += hv * w1.y; acc[6] += hv * w1.z; acc[7] += hv * w1.w;
    }
#pragma unroll
    for (int e = 0; e < 8; ++e)
#pragma unroll
        for (int off = 16; off > 0; off >>= 1)
            acc[e] += __shfl_xor_sync(0xffffffffu, acc[e], off);
    if (lane == 0) {
        float lg[8], mx = -1e30f;
#pragma unroll
        for (int e = 0; e < 8; ++e) { lg[e] = acc[e] + rb3[e]; mx = fmaxf(mx, lg[e]); }
        float sm[8], sum = 0.f;
#pragma unroll
        for (int e = 0; e < 8; ++e) { sm[e] = __expf(lg[e] - mx); sum += sm[e]; }
        const float inv = 1.f / sum;
#pragma unroll
        for (int e = 0; e < 8; ++e) sm[e] *= inv;
        int e1 = 0; float v1 = sm[0];
#pragma unroll
        for (int e = 1; e < 8; ++e) if (sm[e] > v1) { v1 = sm[e]; e1 = e; }
        int e2 = -1; float v2 = -1e30f;
#pragma unroll
        for (int e = 0; e < 8; ++e) {
            if (e == e1) continue;
            if (sm[e] > v2) { v2 = sm[e]; e2 = e; }
        }
        const int j = warp * 2;
        g_expert[j] = e1;     g_gate[j] = v1;
        g_expert[j + 1] = e2; g_gate[j + 1] = v2;
    }
}

// ---------------- per-(b,e) capacity scan: warp ballot scan ----------------
__global__ void scan_capacity()
{
    __shared__ int se[TT * 2];
    const int b = blockIdx.x;
    const int base = b * (TT * 2);
    for (int i = threadIdx.x; i < TT * 2; i += blockDim.x) se[i] = g_expert[base + i];
    __syncthreads();
    const int e = threadIdx.x >> 5;      // warp = expert (8 warps)
    const int lane = threadIdx.x & 31;
    int cnt = 0;
    for (int i0 = 0; i0 < TT * 2; i0 += 32) {
        const bool m = (se[i0 + lane] == e);
        const unsigned bal = __ballot_sync(0xffffffffu, m);
        if (m) {
            const int pos = cnt + __popc(bal & ((1u << lane) - 1));
            g_pos[base + i0 + lane] = (pos < CAP) ? pos : -1;
        }
        cnt += __popc(bal);
    }
}

// ---------------- gather kept tokens ----------------
__global__ void scatter_x()
{
    const int j = blockIdx.x;
    const int pos = g_pos[j];
    if (pos < 0) return;
    const int e = g_expert[j];
    const int b = j / (TT * 2);
    const int t = (j % (TT * 2)) >> 1;
    const uint4* sh = (const uint4*)(g_xh + (size_t)(b * TT + t) * CC);
    uint4* dh = (uint4*)(g_xeh + ((size_t)e * ROWSE + b * CAP + pos) * CC);
    for (int c = threadIdx.x; c < CC / 8; c += blockDim.x) dh[c] = sh[c];
}

// ---------------- combine ----------------
__global__ void combine(float* __restrict__ out)
{
    const int tok = blockIdx.x;
    const int b = tok / TT;
    const int j = tok * 2;
    const int e0 = g_expert[j],     p0 = g_pos[j];     const float w0 = g_gate[j];
    const int e1 = g_expert[j + 1], p1 = g_pos[j + 1]; const float w1 = g_gate[j + 1];
    const float4* y0 = (p0 >= 0) ? (const float4*)(g_ye + ((size_t)e0 * ROWSE + b * CAP + p0) * CC) : nullptr;
    const float4* y1 = (p1 >= 0) ? (const float4*)(g_ye + ((size_t)e1 * ROWSE + b * CAP + p1) * CC) : nullptr;
    float4* o = (float4*)(out + (size_t)tok * CC);
    for (int c = threadIdx.x; c < CC / 4; c += blockDim.x) {
        float4 acc = make_float4(0.f, 0.f, 0.f, 0.f);
        if (y0) { float4 v = y0[c]; acc.x += w0 * v.x; acc.y += w0 * v.y; acc.z += w0 * v.z; acc.w += w0 * v.w; }
        if (y1) { float4 v = y1[c]; acc.x += w1 * v.x; acc.y += w1 * v.y; acc.z += w1 * v.z; acc.w += w1 * v.w; }
        o[c] = acc;
    }
}

// ---------------- launch ----------------
extern "C" void kernel_launch(void* const* d_in, const int* in_sizes, int n_in,
                              void* d_out, int out_size)
{
    const float* x   = (const float*)d_in[0];
    const float* rW1 = (const float*)d_in[1];
    const float* rb1 = (const float*)d_in[2];
    const float* rW2 = (const float*)d_in[3];
    const float* rb2 = (const float*)d_in[4];
    const float* rW3 = (const float*)d_in[5];
    const float* rb3 = (const float*)d_in[6];
    const float* eW1 = (const float*)d_in[7];
    const float* eb1 = (const float*)d_in[8];
    const float* eW2 = (const float*)d_in[9];
    const float* eb2 = (const float*)d_in[10];
    float* out = (float*)d_out;

    __half *xh, *xl, *h1h, *h1l, *xeh, *heh;
    __half *rW1h, *rW1l, *rW2h, *rW2l, *eW1h, *eW2h;
    float *h2, *ye;
    cudaGetSymbolAddress((void**)&xh, g_xh);   cudaGetSymbolAddress((void**)&xl, g_xl);
    cudaGetSymbolAddress((void**)&h1h, g_h1h); cudaGetSymbolAddress((void**)&h1l, g_h1l);
    cudaGetSymbolAddress((void**)&h2, g_h2);
    cudaGetSymbolAddress((void**)&xeh, g_xeh);
    cudaGetSymbolAddress((void**)&heh, g_heh);
    cudaGetSymbolAddress((void**)&ye, g_ye);
    cudaGetSymbolAddress((void**)&rW1h, g_rW1h); cudaGetSymbolAddress((void**)&rW1l, g_rW1l);
    cudaGetSymbolAddress((void**)&rW2h, g_rW2h); cudaGetSymbolAddress((void**)&rW2l, g_rW2l);
    cudaGetSymbolAddress((void**)&eW1h, g_eW1h);
    cudaGetSymbolAddress((void**)&eW2h, g_eW2h);

    const int smem3 = 3 * 4 * TILEB;   // 98304 B
    const int smem1 = 3 * 2 * TILEB;   // 49152 B
    cudaFuncSetAttribute(hmma_gemm<3, true,  1>, cudaFuncAttributeMaxDynamicSharedMemorySize, smem3);
    cudaFuncSetAttribute(hmma_gemm<3, true,  0>, cudaFuncAttributeMaxDynamicSharedMemorySize, smem3);
    cudaFuncSetAttribute(hmma_gemm<1, true,  2>, cudaFuncAttributeMaxDynamicSharedMemorySize, smem1);
    cudaFuncSetAttribute(hmma_gemm<1, false, 0>, cudaFuncAttributeMaxDynamicSharedMemorySize, smem1);

    // input split + weight transpose/split (vectorized half2 stores)
    split_f32<<<(NTOK * CC / 4 + 255) / 256, 256>>>(x, xh, xl, (size_t)NTOK * CC);
    transpose_split_w<<<dim3(HH / 32, CC / 64, 1),  dim3(32, 8)>>>(rW1, rW1h, rW1l, CC, HH, 0, 0);
    transpose_split_w<<<dim3(HH / 32, HH / 64, 1),  dim3(32, 8)>>>(rW2, rW2h, rW2l, HH, HH, 0, 0);
    transpose_split_w<<<dim3(HH / 32, CC / 64, EE), dim3(32, 8)>>>(eW1, eW1h, nullptr, CC, HH,
        (long long)CC * HH, (long long)HH * CC);
    transpose_split_w<<<dim3(CC / 32, HH / 64, EE), dim3(32, 8)>>>(eW2, eW2h, nullptr, HH, CC,
        (long long)HH * CC, (long long)CC * HH);

    // router layer 1: h1 = relu(x @ rW1 + rb1)  (3-pass, split f16 output)
    hmma_gemm<3, true, 1><<<dim3(HH / 128, NTOK / 128, 1), 256, smem3>>>(
        xh, xl, rW1h, rW1l, rb1, nullptr, h1h, h1l, HH, CC, 0, 0, 0, 0);
    // router layer 2: h2 = relu(h1 @ rW2 + rb2)  (3-pass, f32 output)
    hmma_gemm<3, true, 0><<<dim3(HH / 128, NTOK / 128, 1), 256, smem3>>>(
        h1h, h1l, rW2h, rW2l, rb2, h2, nullptr, nullptr, HH, HH, 0, 0, 0, 0);
    // logits + softmax + top2
    router_topk<<<(NTOK * 32) / 256, 256>>>(h2, rW3, rb3);
    // capacity positions
    scan_capacity<<<BB, 256>>>();
    // dispatch
    scatter_x<<<NASN, 128>>>();
    // expert layer 1: he = relu(xe @ eW1[e] + eb1[e])  (1-pass, f16 hi output)
    hmma_gemm<1, true, 2><<<dim3(HH / 128, ROWSE / 128, EE), 256, smem1>>>(
        xeh, nullptr, eW1h, nullptr, eb1, nullptr, heh, nullptr, HH, CC,
        (long long)ROWSE * CC, (long long)HH * CC, HH, (long long)ROWSE * HH);
    // expert layer 2: ye = he @ eW2[e] + eb2[e]  (1-pass, f32 output)
    hmma_gemm<1, false, 0><<<dim3(CC / 128, ROWSE / 128, EE), 256, smem1>>>(
        heh, nullptr, eW2h, nullptr, eb2, ye, nullptr, nullptr, CC, HH,
        (long long)ROWSE * HH, (long long)CC * HH, CC, (long long)ROWSE * CC);
    // combine
    combine<<<NTOK, 256>>>(out);
}

// round 16
// speedup vs baseline: 1.5464x; 1.0063x over previous
#include <cuda_runtime.h>
#include <cuda_fp16.h>
#include <cstdint>

// ---------------- problem constants ----------------
#define BB   8
#define TT   2048
#define CC   1024
#define EE   8
#define HH   4096
#define CAP  320
#define NTOK (BB * TT)
#define NASN (NTOK * 2)
#define ROWSE (BB * CAP)          // 2560

// ---------------- scratch ----------------
static __device__ __half g_xh [(size_t)NTOK * CC],  g_xl [(size_t)NTOK * CC];
static __device__ __half g_h1h[(size_t)NTOK * HH],  g_h1l[(size_t)NTOK * HH];
static __device__ float  g_h2 [(size_t)NTOK * HH];
static __device__ __half g_xeh[(size_t)EE * ROWSE * CC];
static __device__ __half g_heh[(size_t)EE * ROWSE * HH];
static __device__ float  g_ye [(size_t)EE * ROWSE * CC];
static __device__ __half g_rW1h[(size_t)HH * CC],      g_rW1l[(size_t)HH * CC];
static __device__ __half g_rW2h[(size_t)HH * HH],      g_rW2l[(size_t)HH * HH];
static __device__ __half g_eW1h[(size_t)EE * HH * CC];
static __device__ __half g_eW2h[(size_t)EE * CC * HH];
static __device__ int    g_expert[NASN];
static __device__ float  g_gate[NASN];
static __device__ int    g_pos[NASN];

// ---------------- helpers ----------------
__device__ __forceinline__ uint32_t smem_u32(const void* p) {
    uint32_t a;
    asm("{ .reg .u64 t; cvta.to.shared.u64 t, %1; cvt.u32.u64 %0, t; }" : "=r"(a) : "l"(p));
    return a;
}
__device__ __forceinline__ void mma_f16(float* c, const uint32_t* a, uint32_t b0, uint32_t b1) {
    asm("mma.sync.aligned.m16n8k16.row.col.f32.f16.f16.f32 "
        "{%0,%1,%2,%3}, {%4,%5,%6,%7}, {%8,%9}, {%0,%1,%2,%3};"
        : "+f"(c[0]), "+f"(c[1]), "+f"(c[2]), "+f"(c[3])
        : "r"(a[0]), "r"(a[1]), "r"(a[2]), "r"(a[3]), "r"(b0), "r"(b1));
}
#define LDMX4(R, ADDR) \
    asm volatile("ldmatrix.sync.aligned.m8n8.x4.shared.b16 {%0,%1,%2,%3}, [%4];" \
        : "=r"((R)[0]), "=r"((R)[1]), "=r"((R)[2]), "=r"((R)[3]) : "r"(ADDR))
#define CPA16(DST, SRC) \
    asm volatile("cp.async.cg.shared.global [%0], [%1], 16;" :: "r"(DST), "l"(SRC))
#define CPA_COMMIT() asm volatile("cp.async.commit_group;" ::: "memory")
#define CPA_WAIT1()  asm volatile("cp.async.wait_group 1;" ::: "memory")

// tile: 128 rows x 64 B (32 halves). phys(row, chunk) = row*64 + ((chunk ^ ((row>>1)&3))<<4)
#define TILEB 8192
__device__ __forceinline__ uint32_t physoff(int row, int chunk) {
    return (uint32_t)(row * 64 + (((chunk) ^ ((row >> 1) & 3)) << 4));
}

// ---------------- FP16 mma.sync GEMM, cp.async 3-stage, K-chunk 32, 1 sync/chunk ----
// A f16 hi(/lo) [M,K]; Bt f16 hi(/lo) [N,K]. PASSES=3: AhBh+AlBh+AhBl; PASSES=1: AhBh.
// OUT: 0 = f32, 1 = split f16 hi/lo, 2 = f16 hi only.
template <int PASSES, bool RELU, int OUT>
__global__ __launch_bounds__(256, 2)
void hmma_gemm(const __half* __restrict__ Ahg, const __half* __restrict__ Alg,
               const __half* __restrict__ Bhg, const __half* __restrict__ Blg,
               const float* __restrict__ biasg,
               float* __restrict__ Cfg, __half* __restrict__ Chg, __half* __restrict__ Clg,
               int N, int K,
               long long sA, long long sB, long long sBias, long long sC)
{
    constexpr int NT_TILES = (PASSES == 3) ? 4 : 2;
    constexpr uint32_t OFF_AH = 0;
    constexpr uint32_t OFF_AL = TILEB;                 // only PASSES==3
    constexpr uint32_t OFF_BH = (PASSES == 3) ? 2 * TILEB : TILEB;
    constexpr uint32_t OFF_BL = 3 * TILEB;
    constexpr uint32_t STAGE_B = NT_TILES * TILEB;

    extern __shared__ __half sm[];
    const uint32_t sb = smem_u32(sm);
    const int tid  = threadIdx.x;
    const int wid  = tid >> 5;
    const int lane = tid & 31;
    const int q    = lane & 3;

    const size_t aBase = blockIdx.z * sA + (size_t)blockIdx.y * 128 * K;
    const size_t bBase = blockIdx.z * sB + (size_t)blockIdx.x * 128 * K;
    const float* bias  = biasg + blockIdx.z * sBias + blockIdx.x * 128;
    const size_t cBase = blockIdx.z * sC + (size_t)blockIdx.y * 128 * N + blockIdx.x * 128;

    const int wm = (wid & 3) * 32;      // warp tile 32x64
    const int wn = (wid >> 2) * 64;

    // ldmatrix per-lane byte offsets within a tile (swizzled), [mt or p][ks]
    const int r  = lane & 7;
    const int s0 = (lane >> 3) & 1;
    const int s1 = lane >> 4;
    uint32_t aoff[2][2], boff[4][2];
#pragma unroll
    for (int mt = 0; mt < 2; ++mt)
#pragma unroll
        for (int ks = 0; ks < 2; ++ks)
            aoff[mt][ks] = physoff(wm + 16 * mt + r + (s0 << 3), 2 * ks + s1);
#pragma unroll
    for (int p = 0; p < 4; ++p)
#pragma unroll
        for (int ks = 0; ks < 2; ++ks)
            boff[p][ks] = physoff(wn + 16 * p + r + (s1 << 3), 2 * ks + s0);

    // cp.async loader: row = tid>>1, seg = tid&1 -> logical chunks {2seg, 2seg+1}
    const int lrow = tid >> 1;
    const int lseg = tid & 1;
    const char* gAh = (const char*)(Ahg + aBase + (size_t)lrow * K) + lseg * 32;
    const char* gBh = (const char*)(Bhg + bBase + (size_t)lrow * K) + lseg * 32;
    const char* gAl = (PASSES == 3) ? (const char*)(Alg + aBase + (size_t)lrow * K) + lseg * 32 : nullptr;
    const char* gBl = (PASSES == 3) ? (const char*)(Blg + bBase + (size_t)lrow * K) + lseg * 32 : nullptr;
    const uint32_t d0 = physoff(lrow, 2 * lseg);
    const uint32_t d1 = physoff(lrow, 2 * lseg + 1);

    auto issue_chunk = [&](int t, int stage) {
        const uint32_t s = sb + (uint32_t)stage * STAGE_B;
        const int go = t << 6;                        // 64 bytes per chunk
        CPA16(s + OFF_AH + d0, gAh + go);
        CPA16(s + OFF_AH + d1, gAh + go + 16);
        CPA16(s + OFF_BH + d0, gBh + go);
        CPA16(s + OFF_BH + d1, gBh + go + 16);
        if (PASSES == 3) {
            CPA16(s + OFF_AL + d0, gAl + go);
            CPA16(s + OFF_AL + d1, gAl + go + 16);
            CPA16(s + OFF_BL + d0, gBl + go);
            CPA16(s + OFF_BL + d1, gBl + go + 16);
        }
    };

    float acc[2][8][4];
#pragma unroll
    for (int mt = 0; mt < 2; ++mt)
#pragma unroll
        for (int nt = 0; nt < 8; ++nt)
#pragma unroll
            for (int i = 0; i < 4; ++i) acc[mt][nt][i] = 0.f;

    const int T = K >> 5;

    issue_chunk(0, 0); CPA_COMMIT();
    issue_chunk(1, 1); CPA_COMMIT();

    int cur = 0;
    for (int t = 0; t < T; ++t) {
        CPA_WAIT1();                    // chunk t landed
        __syncthreads();                // visibility + all warps done reading stage (t-1)%3
        const int iss = (cur == 0) ? 2 : cur - 1;   // (t+2)%3
        if (t + 2 < T) issue_chunk(t + 2, iss);
        CPA_COMMIT();

        const uint32_t stage = sb + (uint32_t)cur * STAGE_B;
#pragma unroll
        for (int ks = 0; ks < 2; ++ks) {
            uint32_t ah0[4], ah1[4], al0[4], al1[4];
            LDMX4(ah0, stage + OFF_AH + aoff[0][ks]);
            LDMX4(ah1, stage + OFF_AH + aoff[1][ks]);
            if (PASSES == 3) {
                LDMX4(al0, stage + OFF_AL + aoff[0][ks]);
                LDMX4(al1, stage + OFF_AL + aoff[1][ks]);
            }
#pragma unroll
            for (int p = 0; p < 4; ++p) {
                uint32_t bh[4], bl[4];
                LDMX4(bh, stage + OFF_BH + boff[p][ks]);
                if (PASSES == 3) LDMX4(bl, stage + OFF_BL + boff[p][ks]);
#pragma unroll
                for (int sub = 0; sub < 2; ++sub) {
                    const int nt = 2 * p + sub;
                    const uint32_t b0 = bh[2 * sub], b1 = bh[2 * sub + 1];
                    mma_f16(acc[0][nt], ah0, b0, b1);
                    mma_f16(acc[1][nt], ah1, b0, b1);
                    if (PASSES == 3) {
                        mma_f16(acc[0][nt], al0, b0, b1);
                        mma_f16(acc[1][nt], al1, b0, b1);
                        mma_f16(acc[0][nt], ah0, bl[2 * sub], bl[2 * sub + 1]);
                        mma_f16(acc[1][nt], ah1, bl[2 * sub], bl[2 * sub + 1]);
                    }
                }
            }
        }
        cur = (cur == 2) ? 0 : cur + 1;
    }

    // epilogue
    const int gg = lane >> 2;
#pragma unroll
    for (int nt = 0; nt < 8; ++nt) {
        const int c = wn + 8 * nt + 2 * q;
        const float b0 = bias[c], b1 = bias[c + 1];
#pragma unroll
        for (int mt = 0; mt < 2; ++mt) {
            const int rr = wm + 16 * mt + gg;
            float2 v0, v1;
            v0.x = acc[mt][nt][0] + b0; v0.y = acc[mt][nt][1] + b1;
            v1.x = acc[mt][nt][2] + b0; v1.y = acc[mt][nt][3] + b1;
            if (RELU) {
                v0.x = fmaxf(v0.x, 0.f); v0.y = fmaxf(v0.y, 0.f);
                v1.x = fmaxf(v1.x, 0.f); v1.y = fmaxf(v1.y, 0.f);
            }
            if (OUT == 0) {
                *(float2*)(Cfg + cBase + (size_t)rr * N + c)       = v0;
                *(float2*)(Cfg + cBase + (size_t)(rr + 8) * N + c) = v1;
            } else {
                __half2 h0 = __floats2half2_rn(v0.x, v0.y);
                __half2 h1 = __floats2half2_rn(v1.x, v1.y);
                *(__half2*)(Chg + cBase + (size_t)rr * N + c)       = h0;
                *(__half2*)(Chg + cBase + (size_t)(rr + 8) * N + c) = h1;
                if (OUT == 1) {
                    float2 f0 = __half22float2(h0);
                    float2 f1 = __half22float2(h1);
                    __half2 l0 = __floats2half2_rn(v0.x - f0.x, v0.y - f0.y);
                    __half2 l1 = __floats2half2_rn(v1.x - f1.x, v1.y - f1.y);
                    *(__half2*)(Clg + cBase + (size_t)rr * N + c)       = l0;
                    *(__half2*)(Clg + cBase + (size_t)(rr + 8) * N + c) = l1;
                }
            }
        }
    }
}

// ---------------- split fp32 -> f16 hi/lo ----------------
__global__ void split_f32(const float* __restrict__ in, __half* __restrict__ hi,
                          __half* __restrict__ lo, size_t n)
{
    const size_t i = ((size_t)blockIdx.x * blockDim.x + threadIdx.x) * 4;
    if (i >= n) return;
    const float4 v = *(const float4*)(in + i);
    __half2 h0 = __floats2half2_rn(v.x, v.y);
    __half2 h1 = __floats2half2_rn(v.z, v.w);
    float2 f0 = __half22float2(h0);
    float2 f1 = __half22float2(h1);
    __half2 l0 = __floats2half2_rn(v.x - f0.x, v.y - f0.y);
    __half2 l1 = __floats2half2_rn(v.z - f1.x, v.w - f1.y);
    *(__half2*)(hi + i)     = h0;
    *(__half2*)(hi + i + 2) = h1;
    *(__half2*)(lo + i)     = l0;
    *(__half2*)(lo + i + 2) = l1;
}

// ---------------- weight transpose + split (half2 coalesced stores) ----------------
__global__ void transpose_split_w(const float* __restrict__ W,
                                  __half* __restrict__ Wth, __half* __restrict__ Wtl,
                                  int K, int N, long long sIn, long long sOut)
{
    __shared__ float s[64][33];
    const float* Wz = W + blockIdx.z * sIn;
    __half* Wh = Wth + blockIdx.z * sOut;
    __half* Wl = Wtl ? (Wtl + blockIdx.z * sOut) : nullptr;
    const int nb = blockIdx.x * 32, kb = blockIdx.y * 64;
    const int tx = threadIdx.x, ty = threadIdx.y;   // 32 x 8
#pragma unroll
    for (int j = 0; j < 64; j += 8) s[ty + j][tx] = Wz[(size_t)(kb + ty + j) * N + nb + tx];
    __syncthreads();
#pragma unroll
    for (int jj = 0; jj < 4; ++jj) {
        const int n = ty + 8 * jj;
        const float v0 = s[2 * tx][n], v1 = s[2 * tx + 1][n];
        const __half2 h = __floats2half2_rn(v0, v1);
        const size_t o = (size_t)(nb + n) * K + kb + 2 * tx;
        *(__half2*)(Wh + o) = h;
        if (Wl) {
            const float2 f = __half22float2(h);
            *(__half2*)(Wl + o) = __floats2half2_rn(v0 - f.x, v1 - f.y);
        }
    }
}

// ---------------- router final layer ----------------
__global__ void router_topk(const float* __restrict__ h2,
                            const float* __restrict__ rW3,
                            const float* __restrict__ rb3)
{
    const int warp = (blockIdx.x * blockDim.x + threadIdx.x) >> 5;
    const int lane = threadIdx.x & 31;
    if (warp >= NTOK) return;
    const float* hrow = h2 + (size_t)warp * HH;
    float acc[8] = {0.f, 0.f, 0.f, 0.f, 0.f, 0.f, 0.f, 0.f};
    for (int i = lane; i < HH; i += 32) {
        const float hv = hrow[i];
        const float4 w0 = *(const float4*)(rW3 + (size_t)i * 8);
        const float4 w1 = *(const float4*)(rW3 + (size_t)i * 8 + 4);
        acc[0] += hv * w0.x; acc[1] += hv * w0.y; acc[2] += hv * w0.z; acc[3] += hv * w0.w;
        acc[4] += hv * w1.x; acc[5] += hv * w1.y; acc[6] += hv * w1.z; acc[7] += hv * w1.w;
    }
#pragma unroll
    for (int e = 0; e < 8; ++e)
#pragma unroll
        for (int off = 16; off > 0; off >>= 1)
            acc[e] += __shfl_xor_sync(0xffffffffu, acc[e], off);
    if (lane == 0) {
        float lg[8], mx = -1e30f;
#pragma unroll
        for (int e = 0; e < 8; ++e) { lg[e] = acc[e] + rb3[e]; mx = fmaxf(mx, lg[e]); }
        float sm[8], sum = 0.f;
#pragma unroll
        for (int e = 0; e < 8; ++e) { sm[e] = __expf(lg[e] - mx); sum += sm[e]; }
        const float inv = 1.f / sum;
#pragma unroll
        for (int e = 0; e < 8; ++e) sm[e] *= inv;
        int e1 = 0; float v1 = sm[0];
#pragma unroll
        for (int e = 1; e < 8; ++e) if (sm[e] > v1) { v1 = sm[e]; e1 = e; }
        int e2 = -1; float v2 = -1e30f;
#pragma unroll
        for (int e = 0; e < 8; ++e) {
            if (e == e1) continue;
            if (sm[e] > v2) { v2 = sm[e]; e2 = e; }
        }
        const int j = warp * 2;
        g_expert[j] = e1;     g_gate[j] = v1;
        g_expert[j + 1] = e2; g_gate[j + 1] = v2;
    }
}

// ---------------- per-(b,e) capacity scan: warp ballot scan ----------------
__global__ void scan_capacity()
{
    __shared__ int se[TT * 2];
    const int b = blockIdx.x;
    const int base = b * (TT * 2);
    for (int i = threadIdx.x; i < TT * 2; i += blockDim.x) se[i] = g_expert[base + i];
    __syncthreads();
    const int e = threadIdx.x >> 5;
    const int lane = threadIdx.x & 31;
    int cnt = 0;
    for (int i0 = 0; i0 < TT * 2; i0 += 32) {
        const bool m = (se[i0 + lane] == e);
        const unsigned bal = __ballot_sync(0xffffffffu, m);
        if (m) {
            const int pos = cnt + __popc(bal & ((1u << lane) - 1));
            g_pos[base + i0 + lane] = (pos < CAP) ? pos : -1;
        }
        cnt += __popc(bal);
    }
}

// ---------------- gather kept tokens ----------------
__global__ void scatter_x()
{
    const int j = blockIdx.x;
    const int pos = g_pos[j];
    if (pos < 0) return;
    const int e = g_expert[j];
    const int b = j / (TT * 2);
    const int t = (j % (TT * 2)) >> 1;
    const uint4* sh = (const uint4*)(g_xh + (size_t)(b * TT + t) * CC);
    uint4* dh = (uint4*)(g_xeh + ((size_t)e * ROWSE + b * CAP + pos) * CC);
    for (int c = threadIdx.x; c < CC / 8; c += blockDim.x) dh[c] = sh[c];
}

// ---------------- combine ----------------
__global__ void combine(float* __restrict__ out)
{
    const int tok = blockIdx.x;
    const int b = tok / TT;
    const int j = tok * 2;
    const int e0 = g_expert[j],     p0 = g_pos[j];     const float w0 = g_gate[j];
    const int e1 = g_expert[j + 1], p1 = g_pos[j + 1]; const float w1 = g_gate[j + 1];
    const float4* y0 = (p0 >= 0) ? (const float4*)(g_ye + ((size_t)e0 * ROWSE + b * CAP + p0) * CC) : nullptr;
    const float4* y1 = (p1 >= 0) ? (const float4*)(g_ye + ((size_t)e1 * ROWSE + b * CAP + p1) * CC) : nullptr;
    float4* o = (float4*)(out + (size_t)tok * CC);
    for (int c = threadIdx.x; c < CC / 4; c += blockDim.x) {
        float4 acc = make_float4(0.f, 0.f, 0.f, 0.f);
        if (y0) { float4 v = y0[c]; acc.x += w0 * v.x; acc.y += w0 * v.y; acc.z += w0 * v.z; acc.w += w0 * v.w; }
        if (y1) { float4 v = y1[c]; acc.x += w1 * v.x; acc.y += w1 * v.y; acc.z += w1 * v.z; acc.w += w1 * v.w; }
        o[c] = acc;
    }
}

// ---------------- launch ----------------
extern "C" void kernel_launch(void* const* d_in, const int* in_sizes, int n_in,
                              void* d_out, int out_size)
{
    const float* x   = (const float*)d_in[0];
    const float* rW1 = (const float*)d_in[1];
    const float* rb1 = (const float*)d_in[2];
    const float* rW2 = (const float*)d_in[3];
    const float* rb2 = (const float*)d_in[4];
    const float* rW3 = (const float*)d_in[5];
    const float* rb3 = (const float*)d_in[6];
    const float* eW1 = (const float*)d_in[7];
    const float* eb1 = (const float*)d_in[8];
    const float* eW2 = (const float*)d_in[9];
    const float* eb2 = (const float*)d_in[10];
    float* out = (float*)d_out;

    __half *xh, *xl, *h1h, *h1l, *xeh, *heh;
    __half *rW1h, *rW1l, *rW2h, *rW2l, *eW1h, *eW2h;
    float *h2, *ye;
    cudaGetSymbolAddress((void**)&xh, g_xh);   cudaGetSymbolAddress((void**)&xl, g_xl);
    cudaGetSymbolAddress((void**)&h1h, g_h1h); cudaGetSymbolAddress((void**)&h1l, g_h1l);
    cudaGetSymbolAddress((void**)&h2, g_h2);
    cudaGetSymbolAddress((void**)&xeh, g_xeh);
    cudaGetSymbolAddress((void**)&heh, g_heh);
    cudaGetSymbolAddress((void**)&ye, g_ye);
    cudaGetSymbolAddress((void**)&rW1h, g_rW1h); cudaGetSymbolAddress((void**)&rW1l, g_rW1l);
    cudaGetSymbolAddress((void**)&rW2h, g_rW2h); cudaGetSymbolAddress((void**)&rW2l, g_rW2l);
    cudaGetSymbolAddress((void**)&eW1h, g_eW1h);
    cudaGetSymbolAddress((void**)&eW2h, g_eW2h);

    const int smem3 = 3 * 4 * TILEB;   // 98304 B
    const int smem1 = 3 * 2 * TILEB;   // 49152 B
    cudaFuncSetAttribute(hmma_gemm<3, true,  1>, cudaFuncAttributeMaxDynamicSharedMemorySize, smem3);
    cudaFuncSetAttribute(hmma_gemm<3, true,  0>, cudaFuncAttributeMaxDynamicSharedMemorySize, smem3);
    cudaFuncSetAttribute(hmma_gemm<1, true,  2>, cudaFuncAttributeMaxDynamicSharedMemorySize, smem1);
    cudaFuncSetAttribute(hmma_gemm<1, false, 0>, cudaFuncAttributeMaxDynamicSharedMemorySize, smem1);

    // side stream + fork/join events (created once on first, non-captured call;
    // per-call GPU work is identical -> deterministic)
    static cudaStream_t s2 = []() {
        cudaStream_t s; cudaStreamCreateWithFlags(&s, cudaStreamNonBlocking); return s;
    }();
    static cudaEvent_t evFork = []() {
        cudaEvent_t e; cudaEventCreateWithFlags(&e, cudaEventDisableTiming); return e;
    }();
    static cudaEvent_t evJ1 = []() {
        cudaEvent_t e; cudaEventCreateWithFlags(&e, cudaEventDisableTiming); return e;
    }();
    static cudaEvent_t evJ2 = []() {
        cudaEvent_t e; cudaEventCreateWithFlags(&e, cudaEventDisableTiming); return e;
    }();

    // main stream: input split + rW1 transpose (needed by router GEMM1)
    split_f32<<<(NTOK * CC / 4 + 255) / 256, 256>>>(x, xh, xl, (size_t)NTOK * CC);
    transpose_split_w<<<dim3(HH / 32, CC / 64, 1), dim3(32, 8)>>>(rW1, rW1h, rW1l, CC, HH, 0, 0);

    // fork: rW2/eW1/eW2 transposes run on s2, overlapping router GEMM1
    cudaEventRecord(evFork, 0);
    cudaStreamWaitEvent(s2, evFork, 0);
    transpose_split_w<<<dim3(HH / 32, HH / 64, 1), dim3(32, 8), 0, s2>>>(rW2, rW2h, rW2l, HH, HH, 0, 0);
    cudaEventRecord(evJ1, s2);
    transpose_split_w<<<dim3(HH / 32, CC / 64, EE), dim3(32, 8), 0, s2>>>(eW1, eW1h, nullptr, CC, HH,
        (long long)CC * HH, (long long)HH * CC);
    transpose_split_w<<<dim3(CC / 32, HH / 64, EE), dim3(32, 8), 0, s2>>>(eW2, eW2h, nullptr, HH, CC,
        (long long)HH * CC, (long long)CC * HH);
    cudaEventRecord(evJ2, s2);

    // router layer 1: h1 = relu(x @ rW1 + rb1)  (3-pass, split f16 output)
    hmma_gemm<3, true, 1><<<dim3(HH / 128, NTOK / 128, 1), 256, smem3>>>(
        xh, xl, rW1h, rW1l, rb1, nullptr, h1h, h1l, HH, CC, 0, 0, 0, 0);

    // join 1: rW2 ready
    cudaStreamWaitEvent(0, evJ1, 0);
    // router layer 2: h2 = relu(h1 @ rW2 + rb2)  (3-pass, f32 output)
    hmma_gemm<3, true, 0><<<dim3(HH / 128, NTOK / 128, 1), 256, smem3>>>(
        h1h, h1l, rW2h, rW2l, rb2, h2, nullptr, nullptr, HH, HH, 0, 0, 0, 0);
    // logits + softmax + top2
    router_topk<<<(NTOK * 32) / 256, 256>>>(h2, rW3, rb3);
    // capacity positions
    scan_capacity<<<BB, 256>>>();
    // dispatch
    scatter_x<<<NASN, 128>>>();

    // join 2: eW1/eW2 ready
    cudaStreamWaitEvent(0, evJ2, 0);
    // expert layer 1: he = relu(xe @ eW1[e] + eb1[e])  (1-pass, f16 hi output)
    hmma_gemm<1, true, 2><<<dim3(HH / 128, ROWSE / 128, EE), 256, smem1>>>(
        xeh, nullptr, eW1h, nullptr, eb1, nullptr, heh, nullptr, HH, CC,
        (long long)ROWSE * CC, (long long)HH * CC, HH, (long long)ROWSE * HH);
    // expert layer 2: ye = he @ eW2[e] + eb2[e]  (1-pass, f32 output)
    hmma_gemm<1, false, 0><<<dim3(CC / 128, ROWSE / 128, EE), 256, smem1>>>(
        heh, nullptr, eW2h, nullptr, eb2, ye, nullptr, nullptr, CC, HH,
        (long long)ROWSE * HH, (long long)CC * HH, CC, (long long)ROWSE * CC);
    // combine
    combine<<<NTOK, 256>>>(out);
}